// round 16
// baseline (speedup 1.0000x reference)
#include <cuda_runtime.h>
#include <cuda_bf16.h>
#include <math.h>

typedef __nv_bfloat16 bf;

// ---------------- problem constants ----------------
#define DM   1024
#define NHD  16
#define DH   64
#define SEQ  1024
#define NB   2
#define NTOK 2048
#define HFF  4096
#define NV   32000
#define NLE  6
#define NLD  6

// ---------------- bf16 weight pool ----------------
#define O_ENC_QKV  0L
#define O_ENC_PROJ 18874368L
#define O_ENC_FF1  25165824L
#define O_ENC_FF2  50331648L
#define O_DEC_QKV  75497472L
#define O_DEC_PROJ 113246208L
#define O_DEC_FF1  125829120L
#define O_DEC_FF2  150994944L
#define O_GEN      176160768L
#define W_TOTAL    208928768L

__device__ bf g_W[W_TOTAL];

// ---------------- scratch ----------------
__device__ float g_X [(size_t)NTOK*DM];
__device__ float g_Y [(size_t)NTOK*DM];
__device__ bf    g_Hb [(size_t)NTOK*DM];
__device__ bf    g_MEMb[(size_t)NTOK*DM];
__device__ bf    g_QKVb[(size_t)3*NTOK*DM];
__device__ bf    g_AOb [(size_t)NTOK*DM];
__device__ bf    g_FFb [(size_t)NTOK*HFF];

// ---------------- low-level helpers ----------------
__device__ __forceinline__ void cp16(void* d, const void* s){
    unsigned sd = (unsigned)__cvta_generic_to_shared(d);
    asm volatile("cp.async.cg.shared.global [%0], [%1], 16;\n" :: "r"(sd), "l"(s));
}
__device__ __forceinline__ void cpcommit(){ asm volatile("cp.async.commit_group;\n"); }
template<int N> __device__ __forceinline__ void cpwait(){
    asm volatile("cp.async.wait_group %0;\n" :: "n"(N));
}
__device__ __forceinline__ unsigned pack_bf2(float a, float b){
    __nv_bfloat162 h = __floats2bfloat162_rn(a, b);
    return *(unsigned*)&h;
}
__device__ __forceinline__ void ldm4(unsigned &a0, unsigned &a1, unsigned &a2, unsigned &a3,
                                     unsigned addr){
    asm volatile("ldmatrix.sync.aligned.m8n8.x4.shared.b16 {%0,%1,%2,%3}, [%4];"
                 : "=r"(a0),"=r"(a1),"=r"(a2),"=r"(a3) : "r"(addr));
}
__device__ __forceinline__ void ldm4t(unsigned &a0, unsigned &a1, unsigned &a2, unsigned &a3,
                                      unsigned addr){
    asm volatile("ldmatrix.sync.aligned.m8n8.x4.trans.shared.b16 {%0,%1,%2,%3}, [%4];"
                 : "=r"(a0),"=r"(a1),"=r"(a2),"=r"(a3) : "r"(addr));
}
__device__ __forceinline__ void mmabf(float* c, unsigned a0, unsigned a1, unsigned a2, unsigned a3,
                                      unsigned b0, unsigned b1){
    asm volatile("mma.sync.aligned.m16n8k16.row.col.f32.bf16.bf16.f32 "
                 "{%0,%1,%2,%3}, {%4,%5,%6,%7}, {%8,%9}, {%0,%1,%2,%3};"
                 : "+f"(c[0]),"+f"(c[1]),"+f"(c[2]),"+f"(c[3])
                 : "r"(a0),"r"(a1),"r"(a2),"r"(a3),"r"(b0),"r"(b1));
}
__device__ __forceinline__ float gelu1(float x){
    return 0.5f*x*(1.f+erff(x*0.70710678f));
}

// FFMA-pipe exp (no MUFU): exp(x)=2^(x*log2e); deg-5 poly for 2^f, f in [0,1).
// Valid for x <= ~0 (max-subtracted softmax); underflows cleanly to ~0 (incl x=-inf).
__device__ __forceinline__ float fexp(float x){
    float t = fmaxf(x * 1.4426950408889634f, -126.0f);
    int   e = __float2int_rd(t);
    float f = t - (float)e;
    float p = 0.0013333558f;
    p = p*f + 0.0096181291f;
    p = p*f + 0.0555041087f;
    p = p*f + 0.2402265070f;
    p = p*f + 0.6931471806f;
    p = p*f + 1.0f;
    return p * __int_as_float((e + 127) << 23);
}

// ---------------- reductions ----------------
__device__ __forceinline__ float warpSum(float v){
#pragma unroll
    for (int o=16;o>0;o>>=1) v += __shfl_xor_sync(0xffffffffu, v, o);
    return v;
}

// ---------------- f32 -> bf16 converter ----------------
__global__ void cvt_k(const float* __restrict__ s, bf* __restrict__ d, long n){
    long i = ((long)blockIdx.x*blockDim.x + threadIdx.x)*4;
    if (i < n){
        float4 v = *(const float4*)(s+i);
        *(__nv_bfloat162*)(d+i)   = __floats2bfloat162_rn(v.x, v.y);
        *(__nv_bfloat162*)(d+i+2) = __floats2bfloat162_rn(v.z, v.w);
    }
}

// ---------------- GEMM config ----------------
#define BN 128
#define BK 32
#define ASTR 40
#define BSTR 136
#define NSTAGE 4
#define BTILE (BK*BSTR)
#define ATILE128 (128*ASTR)
#define GEMM_SMEM128 ((ATILE128+BTILE)*NSTAGE*2)

__device__ __forceinline__ void epilogue_tile(
    float* acc4, long r0, long r1, long gn, long coff, int ldc,
    const float* bias, const float* res, int doGelu, int outBf,
    float* C, bf* Cb)
{
    float v0 = acc4[0], v1 = acc4[1], v2 = acc4[2], v3 = acc4[3];
    if (bias){
        float b0 = bias[gn], b1 = bias[gn+1];
        v0 += b0; v1 += b1; v2 += b0; v3 += b1;
    }
    if (doGelu){
        v0 = gelu1(v0); v1 = gelu1(v1); v2 = gelu1(v2); v3 = gelu1(v3);
    }
    if (!outBf){
        if (res){
            const float2 q0 = *(const float2*)(res + coff + r0*(long)ldc + gn);
            const float2 q1 = *(const float2*)(res + coff + r1*(long)ldc + gn);
            v0 += q0.x; v1 += q0.y; v2 += q1.x; v3 += q1.y;
        }
        *(float2*)(C + coff + r0*(long)ldc + gn) = make_float2(v0, v1);
        *(float2*)(C + coff + r1*(long)ldc + gn) = make_float2(v2, v3);
    } else {
        *(unsigned*)(Cb + coff + r0*(long)ldc + gn) = pack_bf2(v0, v1);
        *(unsigned*)(Cb + coff + r1*(long)ldc + gn) = pack_bf2(v2, v3);
    }
}

// ---------------- 256-thread variant: 8 warps x 64x32 ----------------
__global__ void __launch_bounds__(256, 2) gemm_ms(
    const bf* __restrict__ A, const bf* __restrict__ B,
    const float* __restrict__ bias, const float* __restrict__ res,
    void* __restrict__ Cv,
    int M, int N, int K, int lda, int ldb, int ldc,
    int doGelu, int outBf,
    long aob, long aoh, long bob, long boh, long biasoh,
    long cob, long coh, int nh)
{
    extern __shared__ __align__(16) unsigned char smraw[];
    bf* As = (bf*)smraw;
    bf* Bs = As + NSTAGE*ATILE128;
    unsigned smA = (unsigned)__cvta_generic_to_shared(As);
    unsigned smB = (unsigned)__cvta_generic_to_shared(Bs);

    int z = blockIdx.z, zb = z/nh, zh = z - zb*nh;
    A += zb*aob + zh*aoh;
    B += zb*bob + zh*boh;
    if (bias) bias += zh*biasoh;
    long coff = zb*cob + zh*coh;

    int tid = threadIdx.x;
    int wid = tid >> 5, lane = tid & 31;
    int wm = wid >> 2, wn = wid & 3;
    long row0 = (long)blockIdx.y * 128;
    long col0 = (long)blockIdx.x * BN;

    const bf* Ag0 = A + (row0 + (tid>>1))*(long)lda + (tid&1)*16;
    bf* Ad0 = As + (tid>>1)*ASTR + (tid&1)*16;
    const bf* Bg0 = B + (long)(tid>>3)*ldb + col0 + (tid&7)*16;
    bf* Bd0 = Bs + (tid>>3)*BSTR + (tid&7)*16;

    auto issue = [&](int kt, int s){
        const bf* ag = Ag0 + kt*BK;
        bf* ad = Ad0 + s*ATILE128;
        cp16(ad,     ag);
        cp16(ad + 8, ag + 8);
        const bf* bg = Bg0 + (long)kt*BK*ldb;
        bf* bd = Bd0 + s*BTILE;
        cp16(bd,     bg);
        cp16(bd + 8, bg + 8);
    };

    float acc[4][4][4];
#pragma unroll
    for (int i=0;i<4;i++)
#pragma unroll
        for (int j=0;j<4;j++)
#pragma unroll
            for (int q=0;q<4;q++) acc[i][j][q] = 0.f;

    unsigned lrow = (unsigned)(lane & 15);
    unsigned lch  = ((unsigned)(lane >> 4)) << 3;

    int KT = K / BK;
    issue(0,0); cpcommit();
    issue(1,1); cpcommit();
    issue(2,2); cpcommit();

    for (int kt = 0; kt < KT; kt++){
        cpwait<2>();
        __syncthreads();
        if (kt+3 < KT) issue(kt+3, (kt+3)&3);
        cpcommit();
        unsigned sa = smA + (unsigned)(kt&3)*ATILE128*2u;
        unsigned sb = smB + (unsigned)(kt&3)*BTILE*2u;
#pragma unroll
        for (int kk = 0; kk < BK; kk += 16){
            unsigned af[4][4];
#pragma unroll
            for (int mi=0;mi<4;mi++){
                unsigned aaddr = sa + (((unsigned)(wm*64) + mi*16u + lrow)*ASTR + kk + lch)*2u;
                ldm4(af[mi][0], af[mi][1], af[mi][2], af[mi][3], aaddr);
            }
#pragma unroll
            for (int ni=0;ni<2;ni++){
                unsigned b0,b1,b2,b3;
                unsigned baddr = sb + ((kk + lrow)*BSTR + wn*32u + ni*16u + lch)*2u;
                ldm4t(b0,b1,b2,b3, baddr);
#pragma unroll
                for (int mi=0;mi<4;mi++){
                    mmabf(acc[mi][2*ni],   af[mi][0],af[mi][1],af[mi][2],af[mi][3], b0,b1);
                    mmabf(acc[mi][2*ni+1], af[mi][0],af[mi][1],af[mi][2],af[mi][3], b2,b3);
                }
            }
        }
    }
    cpwait<0>();

    float* C  = (float*)Cv;
    bf*    Cb = (bf*)Cv;
    int rbase = wm*64 + (lane >> 2);
    int cbase = wn*32 + (lane & 3)*2;
#pragma unroll
    for (int mi=0;mi<4;mi++){
        long r0 = row0 + rbase + mi*16;
        long r1 = r0 + 8;
#pragma unroll
        for (int nj=0;nj<4;nj++){
            long gn = col0 + cbase + nj*8;
            epilogue_tile(acc[mi][nj], r0, r1, gn, coff, ldc, bias, res, doGelu, outBf, C, Cb);
        }
    }
}

// ---------------- 512-thread variant: 16 warps x 32x32 ----------------
__global__ void __launch_bounds__(512, 1) gemm_ms512(
    const bf* __restrict__ A, const bf* __restrict__ B,
    const float* __restrict__ bias, const float* __restrict__ res,
    void* __restrict__ Cv,
    int M, int N, int K, int lda, int ldb, int ldc,
    int doGelu, int outBf,
    long aob, long aoh, long bob, long boh, long biasoh,
    long cob, long coh, int nh)
{
    extern __shared__ __align__(16) unsigned char smraw[];
    bf* As = (bf*)smraw;
    bf* Bs = As + NSTAGE*ATILE128;
    unsigned smA = (unsigned)__cvta_generic_to_shared(As);
    unsigned smB = (unsigned)__cvta_generic_to_shared(Bs);

    int z = blockIdx.z, zb = z/nh, zh = z - zb*nh;
    A += zb*aob + zh*aoh;
    B += zb*bob + zh*boh;
    if (bias) bias += zh*biasoh;
    long coff = zb*cob + zh*coh;

    int tid = threadIdx.x;
    int wid = tid >> 5, lane = tid & 31;
    int wm = wid >> 2, wn = wid & 3;
    long row0 = (long)blockIdx.y * 128;
    long col0 = (long)blockIdx.x * BN;

    const bf* Ag0 = A + (row0 + (tid>>2))*(long)lda + (tid&3)*8;
    bf* Ad0 = As + (tid>>2)*ASTR + (tid&3)*8;
    const bf* Bg0 = B + (long)(tid>>4)*ldb + col0 + (tid&15)*8;
    bf* Bd0 = Bs + (tid>>4)*BSTR + (tid&15)*8;

    auto issue = [&](int kt, int s){
        cp16(Ad0 + s*ATILE128, Ag0 + kt*BK);
        cp16(Bd0 + s*BTILE, Bg0 + (long)kt*BK*ldb);
    };

    float acc[2][4][4];
#pragma unroll
    for (int i=0;i<2;i++)
#pragma unroll
        for (int j=0;j<4;j++)
#pragma unroll
            for (int q=0;q<4;q++) acc[i][j][q] = 0.f;

    unsigned lrow = (unsigned)(lane & 15);
    unsigned lch  = ((unsigned)(lane >> 4)) << 3;

    int KT = K / BK;
    issue(0,0); cpcommit();
    issue(1,1); cpcommit();
    issue(2,2); cpcommit();

    for (int kt = 0; kt < KT; kt++){
        cpwait<2>();
        __syncthreads();
        if (kt+3 < KT) issue(kt+3, (kt+3)&3);
        cpcommit();
        unsigned sa = smA + (unsigned)(kt&3)*ATILE128*2u;
        unsigned sb = smB + (unsigned)(kt&3)*BTILE*2u;
#pragma unroll
        for (int kk = 0; kk < BK; kk += 16){
            unsigned af[2][4];
#pragma unroll
            for (int mi=0;mi<2;mi++){
                unsigned aaddr = sa + (((unsigned)(wm*32) + mi*16u + lrow)*ASTR + kk + lch)*2u;
                ldm4(af[mi][0], af[mi][1], af[mi][2], af[mi][3], aaddr);
            }
#pragma unroll
            for (int ni=0;ni<2;ni++){
                unsigned b0,b1,b2,b3;
                unsigned baddr = sb + ((kk + lrow)*BSTR + wn*32u + ni*16u + lch)*2u;
                ldm4t(b0,b1,b2,b3, baddr);
#pragma unroll
                for (int mi=0;mi<2;mi++){
                    mmabf(acc[mi][2*ni],   af[mi][0],af[mi][1],af[mi][2],af[mi][3], b0,b1);
                    mmabf(acc[mi][2*ni+1], af[mi][0],af[mi][1],af[mi][2],af[mi][3], b2,b3);
                }
            }
        }
    }
    cpwait<0>();

    float* C  = (float*)Cv;
    bf*    Cb = (bf*)Cv;
    int rbase = wm*32 + (lane >> 2);
    int cbase = wn*32 + (lane & 3)*2;
#pragma unroll
    for (int mi=0;mi<2;mi++){
        long r0 = row0 + rbase + mi*16;
        long r1 = r0 + 8;
#pragma unroll
        for (int nj=0;nj<4;nj++){
            long gn = col0 + cbase + nj*8;
            epilogue_tile(acc[mi][nj], r0, r1, gn, coff, ldc, bias, res, doGelu, outBf, C, Cb);
        }
    }
}

// ---------------- flash attention: 64-row KV tiles, 2 CTAs/SM ------------
#define FA_BQ  128
#define FA_SMEM 55296

__global__ void __launch_bounds__(256, 2) flash_k(
    const bf* __restrict__ Qg, const bf* __restrict__ Kg,
    const bf* __restrict__ Vg, bf* __restrict__ Og)
{
    extern __shared__ char smc[];
    unsigned smem0 = (unsigned)__cvta_generic_to_shared(smc);
    unsigned smQ = smem0;
    unsigned smK = smem0 + 18432u;
    unsigned smV = smem0 + 18432u + 18432u;
    bf* gQ = (bf*)smc;
    bf* gK = (bf*)(smc + 18432);
    bf* gV = (bf*)(smc + 18432 + 18432);

    int tid = threadIdx.x;
    int wid = tid >> 5, lane = tid & 31;
    int bh = blockIdx.y;
    long base = ((long)(bh >> 4) * SEQ) * DM + (bh & 15) * DH;
    int q0 = blockIdx.x * FA_BQ;

    {
        int r  = tid >> 1;
        int hc = tid & 1;
        const uint4* qs = (const uint4*)(Qg + base + (long)(q0+r)*DM + hc*32);
        uint4* qd = (uint4*)(gQ + r*72 + hc*32);
#pragma unroll
        for (int i=0;i<4;i++) qd[i] = qs[i];
    }

    int kr = tid >> 2;
    int kc = (tid & 3)*16;
    auto issueKV = [&](int j, int buf){
        long goff = base + (long)(j*64 + kr)*DM + kc;
        bf* kd = gK + buf*(64*72) + kr*72 + kc;
        bf* vd = gV + buf*(64*72) + kr*72 + kc;
        cp16(kd,     Kg + goff);
        cp16(kd + 8, Kg + goff + 8);
        cp16(vd,     Vg + goff);
        cp16(vd + 8, Vg + goff + 8);
    };

    issueKV(0, 0); cpcommit();
    __syncthreads();

    unsigned lrow = (unsigned)(lane & 15);
    unsigned lch  = ((unsigned)(lane >> 4)) << 3;
    unsigned qa[4][4];
    {
        unsigned qaddr = smQ + ((wid*16u + lrow)*72u + lch)*2u;
#pragma unroll
        for (int s=0;s<4;s++)
            ldm4(qa[s][0], qa[s][1], qa[s][2], qa[s][3], qaddr + s*32u);
    }

    float ot[8][4];
#pragma unroll
    for (int d=0;d<8;d++){ ot[d][0]=0.f; ot[d][1]=0.f; ot[d][2]=0.f; ot[d][3]=0.f; }
    float m0 = -INFINITY, m1 = -INFINITY, l0 = 0.f, l1 = 0.f;

    const int NKV = SEQ/64;
    for (int j = 0; j < NKV; j++){
        int cb = j & 1;
        cpwait<0>();
        __syncthreads();
        if (j+1 < NKV) issueKV(j+1, cb^1);
        cpcommit();

        unsigned kb = smK + (unsigned)cb*9216u;
        unsigned vb = smV + (unsigned)cb*9216u;

        float sc[8][4];
#pragma unroll
        for (int t=0;t<8;t++){ sc[t][0]=0.f; sc[t][1]=0.f; sc[t][2]=0.f; sc[t][3]=0.f; }
#pragma unroll
        for (int g=0; g<4; g++){
            unsigned ka = kb + ((g*16u + lrow)*72u + lch)*2u;
#pragma unroll
            for (int s=0; s<4; s++){
                unsigned k0,k1,k2,k3;
                ldm4(k0,k1,k2,k3, ka + s*32u);
                mmabf(sc[2*g],   qa[s][0],qa[s][1],qa[s][2],qa[s][3], k0,k2);
                mmabf(sc[2*g+1], qa[s][0],qa[s][1],qa[s][2],qa[s][3], k1,k3);
            }
        }

        float mx0 = -INFINITY, mx1 = -INFINITY;
#pragma unroll
        for (int t=0;t<8;t++){
            mx0 = fmaxf(mx0, fmaxf(sc[t][0], sc[t][1]));
            mx1 = fmaxf(mx1, fmaxf(sc[t][2], sc[t][3]));
        }
        mx0 = fmaxf(mx0, __shfl_xor_sync(0xffffffffu, mx0, 1));
        mx0 = fmaxf(mx0, __shfl_xor_sync(0xffffffffu, mx0, 2));
        mx1 = fmaxf(mx1, __shfl_xor_sync(0xffffffffu, mx1, 1));
        mx1 = fmaxf(mx1, __shfl_xor_sync(0xffffffffu, mx1, 2));
        float mn0 = fmaxf(m0, mx0), mn1 = fmaxf(m1, mx1);
        float al0 = fexp(m0 - mn0), al1 = fexp(m1 - mn1);
        float s0 = 0.f, s1 = 0.f;
        unsigned pa[4][4];
#pragma unroll
        for (int t=0;t<4;t++){
            float e00 = fexp(sc[2*t][0]-mn0),   e01 = fexp(sc[2*t][1]-mn0);
            float e10 = fexp(sc[2*t][2]-mn1),   e11 = fexp(sc[2*t][3]-mn1);
            float f00 = fexp(sc[2*t+1][0]-mn0), f01 = fexp(sc[2*t+1][1]-mn0);
            float f10 = fexp(sc[2*t+1][2]-mn1), f11 = fexp(sc[2*t+1][3]-mn1);
            s0 += (e00+e01)+(f00+f01);
            s1 += (e10+e11)+(f10+f11);
            pa[t][0] = pack_bf2(e00,e01);
            pa[t][1] = pack_bf2(e10,e11);
            pa[t][2] = pack_bf2(f00,f01);
            pa[t][3] = pack_bf2(f10,f11);
        }
        s0 += __shfl_xor_sync(0xffffffffu, s0, 1);
        s0 += __shfl_xor_sync(0xffffffffu, s0, 2);
        s1 += __shfl_xor_sync(0xffffffffu, s1, 1);
        s1 += __shfl_xor_sync(0xffffffffu, s1, 2);
        l0 = l0*al0 + s0;
        l1 = l1*al1 + s1;
        m0 = mn0; m1 = mn1;
#pragma unroll
        for (int d=0;d<8;d++){
            ot[d][0]*=al0; ot[d][1]*=al0; ot[d][2]*=al1; ot[d][3]*=al1;
        }

#pragma unroll
        for (int s=0; s<4; s++){
            unsigned va = vb + ((s*16u + lrow)*72u + lch)*2u;
#pragma unroll
            for (int d=0; d<4; d++){
                unsigned v0,v1,v2,v3;
                ldm4t(v0,v1,v2,v3, va + d*32u);
                mmabf(ot[2*d],   pa[s][0],pa[s][1],pa[s][2],pa[s][3], v0,v1);
                mmabf(ot[2*d+1], pa[s][0],pa[s][1],pa[s][2],pa[s][3], v2,v3);
            }
        }
    }

    float inv0 = 1.f/l0, inv1 = 1.f/l1;
    int row0 = q0 + wid*16 + (lane >> 2);
    int row1 = row0 + 8;
    bf* o0 = Og + base + (long)row0*DM;
    bf* o1 = Og + base + (long)row1*DM;
    int cb2 = (lane & 3)*2;
#pragma unroll
    for (int d=0; d<8; d++){
        int col = d*8 + cb2;
        *(unsigned*)(o0 + col) = pack_bf2(ot[d][0]*inv0, ot[d][1]*inv0);
        *(unsigned*)(o1 + col) = pack_bf2(ot[d][2]*inv1, ot[d][3]*inv1);
    }
}

// ---------------- embedding + positional encoding ----------------
__global__ void embed_k(const int* __restrict__ tok, const float* __restrict__ emb,
                        float* __restrict__ out)
{
    int t = blockIdx.x;
    int s = t & (SEQ-1);
    int id = tok[t];
    const float* e = emb + (long)id*DM;
    float* o = out + (long)t*DM;
    const float c = -logf(10000.0f) / (float)DM;
    for (int d = threadIdx.x; d < DM; d += blockDim.x) {
        int i2 = d & ~1;
        float ang = (float)s * expf((float)i2 * c);
        float pe = (d & 1) ? cosf(ang) : sinf(ang);
        o[d] = e[d]*32.0f + pe;
    }
}

// ---------------- LayerNorm: warp-per-token ----------------
__global__ void ln_k(const float* __restrict__ x, const float* __restrict__ g,
                     const float* __restrict__ b, bf* __restrict__ out)
{
    int lane = threadIdx.x & 31, w = threadIdx.x >> 5;
    long t = (long)blockIdx.x*8 + w;
    const float4* xr = (const float4*)(x + t*DM);
    float4 v[8];
    float s = 0.f, ss = 0.f;
#pragma unroll
    for (int i=0;i<8;i++){
        v[i] = xr[lane + i*32];
        s  += v[i].x+v[i].y+v[i].z+v[i].w;
        ss += v[i].x*v[i].x+v[i].y*v[i].y+v[i].z*v[i].z+v[i].w*v[i].w;
    }
    s  = warpSum(s);
    ss = warpSum(ss);
    float mean = s * (1.0f/DM);
    float var  = ss * (1.0f/DM) - mean*mean;
    float inv  = rsqrtf(var + 1e-5f);
    uint2* o = (uint2*)(out + t*DM);
#pragma unroll
    for (int i=0;i<8;i++){
        float4 gg = ((const float4*)g)[lane + i*32];
        float4 bb = ((const float4*)b)[lane + i*32];
        uint2 wv;
        wv.x = pack_bf2((v[i].x-mean)*inv*gg.x + bb.x, (v[i].y-mean)*inv*gg.y + bb.y);
        wv.y = pack_bf2((v[i].z-mean)*inv*gg.z + bb.z, (v[i].w-mean)*inv*gg.w + bb.w);
        o[lane + i*32] = wv;
    }
}

// ---------------- log_softmax over NV ----------------
__global__ void logsoftmax_k(float* __restrict__ p)
{
    __shared__ float shm[32], shs[32];
    float* r = p + (long)blockIdx.x * NV;
    int tid = threadIdx.x, lane = tid & 31, w = tid >> 5;

    float m = -3.0e38f, s = 0.f;
    for (int d = tid; d < NV; d += blockDim.x){
        float x = r[d];
        float mn = fmaxf(m, x);
        s = s*fexp(m - mn) + fexp(x - mn);
        m = mn;
    }
#pragma unroll
    for (int o=16;o>0;o>>=1){
        float m2 = __shfl_xor_sync(0xffffffffu, m, o);
        float s2 = __shfl_xor_sync(0xffffffffu, s, o);
        float mn = fmaxf(m, m2);
        s = s*fexp(m-mn) + s2*fexp(m2-mn);
        m = mn;
    }
    if (lane==0){ shm[w] = m; shs[w] = s; }
    __syncthreads();
    if (w==0){
        float mm = (lane < (int)(blockDim.x>>5)) ? shm[lane] : -3.0e38f;
        float ss2 = (lane < (int)(blockDim.x>>5)) ? shs[lane] : 0.f;
#pragma unroll
        for (int o=16;o>0;o>>=1){
            float m2 = __shfl_xor_sync(0xffffffffu, mm, o);
            float s2 = __shfl_xor_sync(0xffffffffu, ss2, o);
            float mn = fmaxf(mm, m2);
            ss2 = ss2*fexp(mm-mn) + s2*fexp(m2-mn);
            mm = mn;
        }
        if (lane==0){ shm[0] = mm; shs[0] = ss2; }
    }
    __syncthreads();
    float lse = shm[0] + logf(shs[0]);
    for (int d = tid; d < NV; d += blockDim.x) r[d] -= lse;
}

// ---------------- host helpers ----------------
static void gemm(const bf* A, const bf* B, const float* bias, const float* res,
                 void* C, int M, int N, int K, int lda, int ldb, int ldc,
                 int gelu, int outBf,
                 long aob=0, long aoh=0, long bob=0, long boh=0, long biasoh=0,
                 long cob=0, long coh=0, int nh=1, int nz=1)
{
    dim3 grid(N/BN, M/128, nz);
    long ctas = (long)grid.x*grid.y*grid.z;
    if (ctas <= 148){
        gemm_ms512<<<grid, 512, GEMM_SMEM128>>>(A,B,bias,res,C,M,N,K,lda,ldb,ldc,gelu,outBf,
                                                aob,aoh,bob,boh,biasoh,cob,coh,nh);
    } else {
        gemm_ms<<<grid, 256, GEMM_SMEM128>>>(A,B,bias,res,C,M,N,K,lda,ldb,ldc,gelu,outBf,
                                             aob,aoh,bob,boh,biasoh,cob,coh,nh);
    }
}

static void cvt(const float* s, bf* d, long n){
    long blocks = (n/4 + 255)/256;
    cvt_k<<<(unsigned)blocks, 256>>>(s, d, n);
}

static void attention(const bf* Hq, const bf* Hkv,
                      const bf* wqkv, const float* bqkv,
                      const bf* wproj, const float* bproj,
                      float* x, int sameKV,
                      bf* QKV, bf* AO)
{
    bf* Q  = QKV;
    bf* Kb = QKV + (size_t)NTOK*DM;
    if (sameKV) {
        gemm(Hq, wqkv, bqkv, nullptr, QKV, NTOK, DM, DM, DM, DM, DM, 0, 1,
             0, 0, 0, (long)DM*DM, DM, 0, (long)NTOK*DM, 3, 3);
    } else {
        gemm(Hq, wqkv, bqkv, nullptr, Q, NTOK, DM, DM, DM, DM, DM, 0, 1);
        gemm(Hkv, wqkv + (size_t)DM*DM, bqkv + DM, nullptr, Kb,
             NTOK, DM, DM, DM, DM, DM, 0, 1,
             0, 0, 0, (long)DM*DM, DM, 0, (long)NTOK*DM, 2, 2);
    }
    bf* Vb = QKV + (size_t)2*NTOK*DM;
    dim3 fgrid(SEQ/FA_BQ, NB*NHD);
    flash_k<<<fgrid, 256, FA_SMEM>>>(Q, Kb, Vb, AO);
    gemm(AO, wproj, bproj, x, x, NTOK, DM, DM, DM, DM, DM, 0, 0);
}

extern "C" void kernel_launch(void* const* d_in, const int* in_sizes, int n_in,
                              void* d_out, int out_size)
{
    const int*   src        = (const int*)  d_in[0];
    const int*   tgt        = (const int*)  d_in[1];
    const float* emb        = (const float*)d_in[5];
    const float* enc_qkv_w  = (const float*)d_in[6];
    const float* enc_qkv_b  = (const float*)d_in[7];
    const float* enc_proj_w = (const float*)d_in[8];
    const float* enc_proj_b = (const float*)d_in[9];
    const float* enc_ff_w1  = (const float*)d_in[10];
    const float* enc_ff_b1  = (const float*)d_in[11];
    const float* enc_ff_w2  = (const float*)d_in[12];
    const float* enc_ff_b2  = (const float*)d_in[13];
    const float* enc_ln_g   = (const float*)d_in[14];
    const float* enc_ln_b   = (const float*)d_in[15];
    const float* enc_norm_g = (const float*)d_in[16];
    const float* enc_norm_b = (const float*)d_in[17];
    const float* dec_qkv_w  = (const float*)d_in[18];
    const float* dec_qkv_b  = (const float*)d_in[19];
    const float* dec_proj_w = (const float*)d_in[20];
    const float* dec_proj_b = (const float*)d_in[21];
    const float* dec_ff_w1  = (const float*)d_in[22];
    const float* dec_ff_b1  = (const float*)d_in[23];
    const float* dec_ff_w2  = (const float*)d_in[24];
    const float* dec_ff_b2  = (const float*)d_in[25];
    const float* dec_ln_g   = (const float*)d_in[26];
    const float* dec_ln_b   = (const float*)d_in[27];
    const float* dec_norm_g = (const float*)d_in[28];
    const float* dec_norm_b = (const float*)d_in[29];
    const float* gen_w      = (const float*)d_in[30];
    const float* gen_b      = (const float*)d_in[31];
    float* out = (float*)d_out;

    cudaFuncSetAttribute(flash_k, cudaFuncAttributeMaxDynamicSharedMemorySize, FA_SMEM);
    cudaFuncSetAttribute(gemm_ms, cudaFuncAttributeMaxDynamicSharedMemorySize, GEMM_SMEM128);
    cudaFuncSetAttribute(gemm_ms512, cudaFuncAttributeMaxDynamicSharedMemorySize, GEMM_SMEM128);

    float *X,*Y;
    bf *Hb,*MEMb,*QKVb,*AOb,*FFb,*W;
    cudaGetSymbolAddress((void**)&X,    g_X);
    cudaGetSymbolAddress((void**)&Y,    g_Y);
    cudaGetSymbolAddress((void**)&Hb,   g_Hb);
    cudaGetSymbolAddress((void**)&MEMb, g_MEMb);
    cudaGetSymbolAddress((void**)&QKVb, g_QKVb);
    cudaGetSymbolAddress((void**)&AOb,  g_AOb);
    cudaGetSymbolAddress((void**)&FFb,  g_FFb);
    cudaGetSymbolAddress((void**)&W,    g_W);

    // ---- one-time (per replay) weight conversion ----
    cvt(enc_qkv_w,  W + O_ENC_QKV,  (long)NLE*3*DM*DM);
    cvt(enc_proj_w, W + O_ENC_PROJ, (long)NLE*DM*DM);
    cvt(enc_ff_w1,  W + O_ENC_FF1,  (long)NLE*DM*HFF);
    cvt(enc_ff_w2,  W + O_ENC_FF2,  (long)NLE*HFF*DM);
    cvt(dec_qkv_w,  W + O_DEC_QKV,  (long)NLD*2*3*DM*DM);
    cvt(dec_proj_w, W + O_DEC_PROJ, (long)NLD*2*DM*DM);
    cvt(dec_ff_w1,  W + O_DEC_FF1,  (long)NLD*DM*HFF);
    cvt(dec_ff_w2,  W + O_DEC_FF2,  (long)NLD*HFF*DM);
    cvt(gen_w,      W + O_GEN,      (long)DM*NV);

    // ---------------- encoder ----------------
    embed_k<<<NTOK,256>>>(src, emb, X);
    for (int l = 0; l < NLE; l++) {
        ln_k<<<NTOK/8,256>>>(X, enc_ln_g + (size_t)(l*2+0)*DM, enc_ln_b + (size_t)(l*2+0)*DM, Hb);
        attention(Hb, Hb,
                  W + O_ENC_QKV + (long)l*3*DM*DM, enc_qkv_b + (size_t)l*3*DM,
                  W + O_ENC_PROJ + (long)l*DM*DM,  enc_proj_b + (size_t)l*DM,
                  X, 1, QKVb, AOb);
        ln_k<<<NTOK/8,256>>>(X, enc_ln_g + (size_t)(l*2+1)*DM, enc_ln_b + (size_t)(l*2+1)*DM, Hb);
        gemm(Hb, W + O_ENC_FF1 + (long)l*DM*HFF, enc_ff_b1 + (size_t)l*HFF, nullptr, FFb,
             NTOK, HFF, DM, DM, HFF, HFF, 1, 1);
        gemm(FFb, W + O_ENC_FF2 + (long)l*HFF*DM, enc_ff_b2 + (size_t)l*DM, X, X,
             NTOK, DM, HFF, HFF, DM, DM, 1, 0);
    }
    ln_k<<<NTOK/8,256>>>(X, enc_norm_g, enc_norm_b, MEMb);

    // ---------------- decoder ----------------
    embed_k<<<NTOK,256>>>(tgt, emb, Y);
    for (int l = 0; l < NLD; l++) {
        ln_k<<<NTOK/8,256>>>(Y, dec_ln_g + (size_t)(l*3+0)*DM, dec_ln_b + (size_t)(l*3+0)*DM, Hb);
        attention(Hb, Hb,
                  W + O_DEC_QKV + (long)(l*2+0)*3*DM*DM, dec_qkv_b + (size_t)(l*2+0)*3*DM,
                  W + O_DEC_PROJ + (long)(l*2+0)*DM*DM,  dec_proj_b + (size_t)(l*2+0)*DM,
                  Y, 1, QKVb, AOb);
        ln_k<<<NTOK/8,256>>>(Y, dec_ln_g + (size_t)(l*3+1)*DM, dec_ln_b + (size_t)(l*3+1)*DM, Hb);
        attention(Hb, MEMb,
                  W + O_DEC_QKV + (long)(l*2+1)*3*DM*DM, dec_qkv_b + (size_t)(l*2+1)*3*DM,
                  W + O_DEC_PROJ + (long)(l*2+1)*DM*DM,  dec_proj_b + (size_t)(l*2+1)*DM,
                  Y, 0, QKVb, AOb);
        ln_k<<<NTOK/8,256>>>(Y, dec_ln_g + (size_t)(l*3+2)*DM, dec_ln_b + (size_t)(l*3+2)*DM, Hb);
        gemm(Hb, W + O_DEC_FF1 + (long)l*DM*HFF, dec_ff_b1 + (size_t)l*HFF, nullptr, FFb,
             NTOK, HFF, DM, DM, HFF, HFF, 1, 1);
        gemm(FFb, W + O_DEC_FF2 + (long)l*HFF*DM, dec_ff_b2 + (size_t)l*DM, Y, Y,
             NTOK, DM, HFF, HFF, DM, DM, 1, 0);
    }
    ln_k<<<NTOK/8,256>>>(Y, dec_norm_g, dec_norm_b, Hb);

    // ---------------- generator + log_softmax ----------------
    gemm(Hb, W + O_GEN, gen_b, nullptr, out, NTOK, NV, DM, DM, NV, NV, 0, 0);
    logsoftmax_k<<<NTOK,256>>>(out);
}

// round 17
// speedup vs baseline: 1.0439x; 1.0439x over previous
#include <cuda_runtime.h>
#include <cuda_bf16.h>
#include <math.h>

typedef __nv_bfloat16 bf;

// ---------------- problem constants ----------------
#define DM   1024
#define NHD  16
#define DH   64
#define SEQ  1024
#define NB   2
#define NTOK 2048
#define HFF  4096
#define NV   32000
#define NLE  6
#define NLD  6

// ---------------- bf16 weight pool ----------------
#define O_ENC_QKV  0L
#define O_ENC_PROJ 18874368L
#define O_ENC_FF1  25165824L
#define O_ENC_FF2  50331648L
#define O_DEC_QKV  75497472L
#define O_DEC_PROJ 113246208L
#define O_DEC_FF1  125829120L
#define O_DEC_FF2  150994944L
#define O_GEN      176160768L
#define W_TOTAL    208928768L

__device__ bf g_W[W_TOTAL];

// ---------------- scratch ----------------
__device__ float g_X [(size_t)NTOK*DM];
__device__ float g_Y [(size_t)NTOK*DM];
__device__ bf    g_Hb [(size_t)NTOK*DM];
__device__ bf    g_MEMb[(size_t)NTOK*DM];
__device__ bf    g_QKVb[(size_t)3*NTOK*DM];
__device__ bf    g_AOb [(size_t)NTOK*DM];
__device__ bf    g_FFb [(size_t)NTOK*HFF];

// ---------------- low-level helpers ----------------
__device__ __forceinline__ void cp16(void* d, const void* s){
    unsigned sd = (unsigned)__cvta_generic_to_shared(d);
    asm volatile("cp.async.cg.shared.global [%0], [%1], 16;\n" :: "r"(sd), "l"(s));
}
__device__ __forceinline__ void cpcommit(){ asm volatile("cp.async.commit_group;\n"); }
template<int N> __device__ __forceinline__ void cpwait(){
    asm volatile("cp.async.wait_group %0;\n" :: "n"(N));
}
__device__ __forceinline__ unsigned pack_bf2(float a, float b){
    __nv_bfloat162 h = __floats2bfloat162_rn(a, b);
    return *(unsigned*)&h;
}
__device__ __forceinline__ void ldm4(unsigned &a0, unsigned &a1, unsigned &a2, unsigned &a3,
                                     unsigned addr){
    asm volatile("ldmatrix.sync.aligned.m8n8.x4.shared.b16 {%0,%1,%2,%3}, [%4];"
                 : "=r"(a0),"=r"(a1),"=r"(a2),"=r"(a3) : "r"(addr));
}
__device__ __forceinline__ void ldm4t(unsigned &a0, unsigned &a1, unsigned &a2, unsigned &a3,
                                      unsigned addr){
    asm volatile("ldmatrix.sync.aligned.m8n8.x4.trans.shared.b16 {%0,%1,%2,%3}, [%4];"
                 : "=r"(a0),"=r"(a1),"=r"(a2),"=r"(a3) : "r"(addr));
}
__device__ __forceinline__ void mmabf(float* c, unsigned a0, unsigned a1, unsigned a2, unsigned a3,
                                      unsigned b0, unsigned b1){
    asm volatile("mma.sync.aligned.m16n8k16.row.col.f32.bf16.bf16.f32 "
                 "{%0,%1,%2,%3}, {%4,%5,%6,%7}, {%8,%9}, {%0,%1,%2,%3};"
                 : "+f"(c[0]),"+f"(c[1]),"+f"(c[2]),"+f"(c[3])
                 : "r"(a0),"r"(a1),"r"(a2),"r"(a3),"r"(b0),"r"(b1));
}
__device__ __forceinline__ float gelu1(float x){
    return 0.5f*x*(1.f+erff(x*0.70710678f));
}

// ---------------- reductions ----------------
__device__ __forceinline__ float warpSum(float v){
#pragma unroll
    for (int o=16;o>0;o>>=1) v += __shfl_xor_sync(0xffffffffu, v, o);
    return v;
}

// ---------------- f32 -> bf16 converter (8 elems/thread, 16B store) ------
__global__ void cvt_k(const float* __restrict__ s, bf* __restrict__ d, long n){
    long i = ((long)blockIdx.x*blockDim.x + threadIdx.x)*8;
    if (i < n){
        float4 a = *(const float4*)(s+i);
        float4 b = *(const float4*)(s+i+4);
        uint4 w;
        w.x = pack_bf2(a.x, a.y);
        w.y = pack_bf2(a.z, a.w);
        w.z = pack_bf2(b.x, b.y);
        w.w = pack_bf2(b.z, b.w);
        *(uint4*)(d+i) = w;
    }
}

// ---------------- GEMM config ----------------
#define BN 128
#define BK 32
#define ASTR 40
#define BSTR 136
#define NSTAGE 4
#define BTILE (BK*BSTR)
#define ATILE128 (128*ASTR)
#define GEMM_SMEM128 ((ATILE128+BTILE)*NSTAGE*2)

__device__ __forceinline__ void epilogue_tile(
    float* acc4, long r0, long r1, long gn, long coff, int ldc,
    const float* bias, const float* res, int doGelu, int outBf,
    float* C, bf* Cb)
{
    float v0 = acc4[0], v1 = acc4[1], v2 = acc4[2], v3 = acc4[3];
    if (bias){
        float b0 = bias[gn], b1 = bias[gn+1];
        v0 += b0; v1 += b1; v2 += b0; v3 += b1;
    }
    if (doGelu){
        v0 = gelu1(v0); v1 = gelu1(v1); v2 = gelu1(v2); v3 = gelu1(v3);
    }
    if (!outBf){
        if (res){
            const float2 q0 = *(const float2*)(res + coff + r0*(long)ldc + gn);
            const float2 q1 = *(const float2*)(res + coff + r1*(long)ldc + gn);
            v0 += q0.x; v1 += q0.y; v2 += q1.x; v3 += q1.y;
        }
        *(float2*)(C + coff + r0*(long)ldc + gn) = make_float2(v0, v1);
        *(float2*)(C + coff + r1*(long)ldc + gn) = make_float2(v2, v3);
    } else {
        *(unsigned*)(Cb + coff + r0*(long)ldc + gn) = pack_bf2(v0, v1);
        *(unsigned*)(Cb + coff + r1*(long)ldc + gn) = pack_bf2(v2, v3);
    }
}

// ---------------- 256-thread variant: 8 warps x 64x32 ----------------
__global__ void __launch_bounds__(256, 2) gemm_ms(
    const bf* __restrict__ A, const bf* __restrict__ B,
    const float* __restrict__ bias, const float* __restrict__ res,
    void* __restrict__ Cv,
    int M, int N, int K, int lda, int ldb, int ldc,
    int doGelu, int outBf,
    long aob, long aoh, long bob, long boh, long biasoh,
    long cob, long coh, int nh)
{
    extern __shared__ __align__(16) unsigned char smraw[];
    bf* As = (bf*)smraw;
    bf* Bs = As + NSTAGE*ATILE128;
    unsigned smA = (unsigned)__cvta_generic_to_shared(As);
    unsigned smB = (unsigned)__cvta_generic_to_shared(Bs);

    int z = blockIdx.z, zb = z/nh, zh = z - zb*nh;
    A += zb*aob + zh*aoh;
    B += zb*bob + zh*boh;
    if (bias) bias += zh*biasoh;
    long coff = zb*cob + zh*coh;

    int tid = threadIdx.x;
    int wid = tid >> 5, lane = tid & 31;
    int wm = wid >> 2, wn = wid & 3;
    long row0 = (long)blockIdx.y * 128;
    long col0 = (long)blockIdx.x * BN;

    const bf* Ag0 = A + (row0 + (tid>>1))*(long)lda + (tid&1)*16;
    bf* Ad0 = As + (tid>>1)*ASTR + (tid&1)*16;
    const bf* Bg0 = B + (long)(tid>>3)*ldb + col0 + (tid&7)*16;
    bf* Bd0 = Bs + (tid>>3)*BSTR + (tid&7)*16;

    auto issue = [&](int kt, int s){
        const bf* ag = Ag0 + kt*BK;
        bf* ad = Ad0 + s*ATILE128;
        cp16(ad,     ag);
        cp16(ad + 8, ag + 8);
        const bf* bg = Bg0 + (long)kt*BK*ldb;
        bf* bd = Bd0 + s*BTILE;
        cp16(bd,     bg);
        cp16(bd + 8, bg + 8);
    };

    float acc[4][4][4];
#pragma unroll
    for (int i=0;i<4;i++)
#pragma unroll
        for (int j=0;j<4;j++)
#pragma unroll
            for (int q=0;q<4;q++) acc[i][j][q] = 0.f;

    unsigned lrow = (unsigned)(lane & 15);
    unsigned lch  = ((unsigned)(lane >> 4)) << 3;

    int KT = K / BK;
    issue(0,0); cpcommit();
    issue(1,1); cpcommit();
    issue(2,2); cpcommit();

    for (int kt = 0; kt < KT; kt++){
        cpwait<2>();
        __syncthreads();
        if (kt+3 < KT) issue(kt+3, (kt+3)&3);
        cpcommit();
        unsigned sa = smA + (unsigned)(kt&3)*ATILE128*2u;
        unsigned sb = smB + (unsigned)(kt&3)*BTILE*2u;
#pragma unroll
        for (int kk = 0; kk < BK; kk += 16){
            unsigned af[4][4];
#pragma unroll
            for (int mi=0;mi<4;mi++){
                unsigned aaddr = sa + (((unsigned)(wm*64) + mi*16u + lrow)*ASTR + kk + lch)*2u;
                ldm4(af[mi][0], af[mi][1], af[mi][2], af[mi][3], aaddr);
            }
#pragma unroll
            for (int ni=0;ni<2;ni++){
                unsigned b0,b1,b2,b3;
                unsigned baddr = sb + ((kk + lrow)*BSTR + wn*32u + ni*16u + lch)*2u;
                ldm4t(b0,b1,b2,b3, baddr);
#pragma unroll
                for (int mi=0;mi<4;mi++){
                    mmabf(acc[mi][2*ni],   af[mi][0],af[mi][1],af[mi][2],af[mi][3], b0,b1);
                    mmabf(acc[mi][2*ni+1], af[mi][0],af[mi][1],af[mi][2],af[mi][3], b2,b3);
                }
            }
        }
    }
    cpwait<0>();

    float* C  = (float*)Cv;
    bf*    Cb = (bf*)Cv;
    int rbase = wm*64 + (lane >> 2);
    int cbase = wn*32 + (lane & 3)*2;
#pragma unroll
    for (int mi=0;mi<4;mi++){
        long r0 = row0 + rbase + mi*16;
        long r1 = r0 + 8;
#pragma unroll
        for (int nj=0;nj<4;nj++){
            long gn = col0 + cbase + nj*8;
            epilogue_tile(acc[mi][nj], r0, r1, gn, coff, ldc, bias, res, doGelu, outBf, C, Cb);
        }
    }
}

// ---------------- 512-thread variant: 16 warps x 32x32 ----------------
__global__ void __launch_bounds__(512, 1) gemm_ms512(
    const bf* __restrict__ A, const bf* __restrict__ B,
    const float* __restrict__ bias, const float* __restrict__ res,
    void* __restrict__ Cv,
    int M, int N, int K, int lda, int ldb, int ldc,
    int doGelu, int outBf,
    long aob, long aoh, long bob, long boh, long biasoh,
    long cob, long coh, int nh)
{
    extern __shared__ __align__(16) unsigned char smraw[];
    bf* As = (bf*)smraw;
    bf* Bs = As + NSTAGE*ATILE128;
    unsigned smA = (unsigned)__cvta_generic_to_shared(As);
    unsigned smB = (unsigned)__cvta_generic_to_shared(Bs);

    int z = blockIdx.z, zb = z/nh, zh = z - zb*nh;
    A += zb*aob + zh*aoh;
    B += zb*bob + zh*boh;
    if (bias) bias += zh*biasoh;
    long coff = zb*cob + zh*coh;

    int tid = threadIdx.x;
    int wid = tid >> 5, lane = tid & 31;
    int wm = wid >> 2, wn = wid & 3;
    long row0 = (long)blockIdx.y * 128;
    long col0 = (long)blockIdx.x * BN;

    const bf* Ag0 = A + (row0 + (tid>>2))*(long)lda + (tid&3)*8;
    bf* Ad0 = As + (tid>>2)*ASTR + (tid&3)*8;
    const bf* Bg0 = B + (long)(tid>>4)*ldb + col0 + (tid&15)*8;
    bf* Bd0 = Bs + (tid>>4)*BSTR + (tid&15)*8;

    auto issue = [&](int kt, int s){
        cp16(Ad0 + s*ATILE128, Ag0 + kt*BK);
        cp16(Bd0 + s*BTILE, Bg0 + (long)kt*BK*ldb);
    };

    float acc[2][4][4];
#pragma unroll
    for (int i=0;i<2;i++)
#pragma unroll
        for (int j=0;j<4;j++)
#pragma unroll
            for (int q=0;q<4;q++) acc[i][j][q] = 0.f;

    unsigned lrow = (unsigned)(lane & 15);
    unsigned lch  = ((unsigned)(lane >> 4)) << 3;

    int KT = K / BK;
    issue(0,0); cpcommit();
    issue(1,1); cpcommit();
    issue(2,2); cpcommit();

    for (int kt = 0; kt < KT; kt++){
        cpwait<2>();
        __syncthreads();
        if (kt+3 < KT) issue(kt+3, (kt+3)&3);
        cpcommit();
        unsigned sa = smA + (unsigned)(kt&3)*ATILE128*2u;
        unsigned sb = smB + (unsigned)(kt&3)*BTILE*2u;
#pragma unroll
        for (int kk = 0; kk < BK; kk += 16){
            unsigned af[2][4];
#pragma unroll
            for (int mi=0;mi<2;mi++){
                unsigned aaddr = sa + (((unsigned)(wm*32) + mi*16u + lrow)*ASTR + kk + lch)*2u;
                ldm4(af[mi][0], af[mi][1], af[mi][2], af[mi][3], aaddr);
            }
#pragma unroll
            for (int ni=0;ni<2;ni++){
                unsigned b0,b1,b2,b3;
                unsigned baddr = sb + ((kk + lrow)*BSTR + wn*32u + ni*16u + lch)*2u;
                ldm4t(b0,b1,b2,b3, baddr);
#pragma unroll
                for (int mi=0;mi<2;mi++){
                    mmabf(acc[mi][2*ni],   af[mi][0],af[mi][1],af[mi][2],af[mi][3], b0,b1);
                    mmabf(acc[mi][2*ni+1], af[mi][0],af[mi][1],af[mi][2],af[mi][3], b2,b3);
                }
            }
        }
    }
    cpwait<0>();

    float* C  = (float*)Cv;
    bf*    Cb = (bf*)Cv;
    int rbase = wm*32 + (lane >> 2);
    int cbase = wn*32 + (lane & 3)*2;
#pragma unroll
    for (int mi=0;mi<2;mi++){
        long r0 = row0 + rbase + mi*16;
        long r1 = r0 + 8;
#pragma unroll
        for (int nj=0;nj<4;nj++){
            long gn = col0 + cbase + nj*8;
            epilogue_tile(acc[mi][nj], r0, r1, gn, coff, ldc, bias, res, doGelu, outBf, C, Cb);
        }
    }
}

// ---------------- flash attention: 64-row KV tiles, 2 CTAs/SM ------------
#define FA_BQ  128
#define FA_SMEM 55296

__global__ void __launch_bounds__(256, 2) flash_k(
    const bf* __restrict__ Qg, const bf* __restrict__ Kg,
    const bf* __restrict__ Vg, bf* __restrict__ Og)
{
    extern __shared__ char smc[];
    unsigned smem0 = (unsigned)__cvta_generic_to_shared(smc);
    unsigned smQ = smem0;
    unsigned smK = smem0 + 18432u;
    unsigned smV = smem0 + 18432u + 18432u;
    bf* gQ = (bf*)smc;
    bf* gK = (bf*)(smc + 18432);
    bf* gV = (bf*)(smc + 18432 + 18432);

    int tid = threadIdx.x;
    int wid = tid >> 5, lane = tid & 31;
    int bh = blockIdx.y;
    long base = ((long)(bh >> 4) * SEQ) * DM + (bh & 15) * DH;
    int q0 = blockIdx.x * FA_BQ;

    {
        int r  = tid >> 1;
        int hc = tid & 1;
        const uint4* qs = (const uint4*)(Qg + base + (long)(q0+r)*DM + hc*32);
        uint4* qd = (uint4*)(gQ + r*72 + hc*32);
#pragma unroll
        for (int i=0;i<4;i++) qd[i] = qs[i];
    }

    int kr = tid >> 2;
    int kc = (tid & 3)*16;
    auto issueKV = [&](int j, int buf){
        long goff = base + (long)(j*64 + kr)*DM + kc;
        bf* kd = gK + buf*(64*72) + kr*72 + kc;
        bf* vd = gV + buf*(64*72) + kr*72 + kc;
        cp16(kd,     Kg + goff);
        cp16(kd + 8, Kg + goff + 8);
        cp16(vd,     Vg + goff);
        cp16(vd + 8, Vg + goff + 8);
    };

    issueKV(0, 0); cpcommit();
    __syncthreads();

    unsigned lrow = (unsigned)(lane & 15);
    unsigned lch  = ((unsigned)(lane >> 4)) << 3;
    unsigned qa[4][4];
    {
        unsigned qaddr = smQ + ((wid*16u + lrow)*72u + lch)*2u;
#pragma unroll
        for (int s=0;s<4;s++)
            ldm4(qa[s][0], qa[s][1], qa[s][2], qa[s][3], qaddr + s*32u);
    }

    float ot[8][4];
#pragma unroll
    for (int d=0;d<8;d++){ ot[d][0]=0.f; ot[d][1]=0.f; ot[d][2]=0.f; ot[d][3]=0.f; }
    float m0 = -INFINITY, m1 = -INFINITY, l0 = 0.f, l1 = 0.f;

    const int NKV = SEQ/64;
    for (int j = 0; j < NKV; j++){
        int cb = j & 1;
        cpwait<0>();
        __syncthreads();
        if (j+1 < NKV) issueKV(j+1, cb^1);
        cpcommit();

        unsigned kb = smK + (unsigned)cb*9216u;
        unsigned vb = smV + (unsigned)cb*9216u;

        float sc[8][4];
#pragma unroll
        for (int t=0;t<8;t++){ sc[t][0]=0.f; sc[t][1]=0.f; sc[t][2]=0.f; sc[t][3]=0.f; }
#pragma unroll
        for (int g=0; g<4; g++){
            unsigned ka = kb + ((g*16u + lrow)*72u + lch)*2u;
#pragma unroll
            for (int s=0; s<4; s++){
                unsigned k0,k1,k2,k3;
                ldm4(k0,k1,k2,k3, ka + s*32u);
                mmabf(sc[2*g],   qa[s][0],qa[s][1],qa[s][2],qa[s][3], k0,k2);
                mmabf(sc[2*g+1], qa[s][0],qa[s][1],qa[s][2],qa[s][3], k1,k3);
            }
        }

        float mx0 = -INFINITY, mx1 = -INFINITY;
#pragma unroll
        for (int t=0;t<8;t++){
            mx0 = fmaxf(mx0, fmaxf(sc[t][0], sc[t][1]));
            mx1 = fmaxf(mx1, fmaxf(sc[t][2], sc[t][3]));
        }
        mx0 = fmaxf(mx0, __shfl_xor_sync(0xffffffffu, mx0, 1));
        mx0 = fmaxf(mx0, __shfl_xor_sync(0xffffffffu, mx0, 2));
        mx1 = fmaxf(mx1, __shfl_xor_sync(0xffffffffu, mx1, 1));
        mx1 = fmaxf(mx1, __shfl_xor_sync(0xffffffffu, mx1, 2));
        float mn0 = fmaxf(m0, mx0), mn1 = fmaxf(m1, mx1);
        float al0 = __expf(m0 - mn0), al1 = __expf(m1 - mn1);
        float s0 = 0.f, s1 = 0.f;
        unsigned pa[4][4];
#pragma unroll
        for (int t=0;t<4;t++){
            float e00 = __expf(sc[2*t][0]-mn0),   e01 = __expf(sc[2*t][1]-mn0);
            float e10 = __expf(sc[2*t][2]-mn1),   e11 = __expf(sc[2*t][3]-mn1);
            float f00 = __expf(sc[2*t+1][0]-mn0), f01 = __expf(sc[2*t+1][1]-mn0);
            float f10 = __expf(sc[2*t+1][2]-mn1), f11 = __expf(sc[2*t+1][3]-mn1);
            s0 += (e00+e01)+(f00+f01);
            s1 += (e10+e11)+(f10+f11);
            pa[t][0] = pack_bf2(e00,e01);
            pa[t][1] = pack_bf2(e10,e11);
            pa[t][2] = pack_bf2(f00,f01);
            pa[t][3] = pack_bf2(f10,f11);
        }
        s0 += __shfl_xor_sync(0xffffffffu, s0, 1);
        s0 += __shfl_xor_sync(0xffffffffu, s0, 2);
        s1 += __shfl_xor_sync(0xffffffffu, s1, 1);
        s1 += __shfl_xor_sync(0xffffffffu, s1, 2);
        l0 = l0*al0 + s0;
        l1 = l1*al1 + s1;
        m0 = mn0; m1 = mn1;
#pragma unroll
        for (int d=0;d<8;d++){
            ot[d][0]*=al0; ot[d][1]*=al0; ot[d][2]*=al1; ot[d][3]*=al1;
        }

#pragma unroll
        for (int s=0; s<4; s++){
            unsigned va = vb + ((s*16u + lrow)*72u + lch)*2u;
#pragma unroll
            for (int d=0; d<4; d++){
                unsigned v0,v1,v2,v3;
                ldm4t(v0,v1,v2,v3, va + d*32u);
                mmabf(ot[2*d],   pa[s][0],pa[s][1],pa[s][2],pa[s][3], v0,v1);
                mmabf(ot[2*d+1], pa[s][0],pa[s][1],pa[s][2],pa[s][3], v2,v3);
            }
        }
    }

    float inv0 = 1.f/l0, inv1 = 1.f/l1;
    int row0 = q0 + wid*16 + (lane >> 2);
    int row1 = row0 + 8;
    bf* o0 = Og + base + (long)row0*DM;
    bf* o1 = Og + base + (long)row1*DM;
    int cb2 = (lane & 3)*2;
#pragma unroll
    for (int d=0; d<8; d++){
        int col = d*8 + cb2;
        *(unsigned*)(o0 + col) = pack_bf2(ot[d][0]*inv0, ot[d][1]*inv0);
        *(unsigned*)(o1 + col) = pack_bf2(ot[d][2]*inv1, ot[d][3]*inv1);
    }
}

// ---------------- embedding + positional encoding ----------------
__global__ void embed_k(const int* __restrict__ tok, const float* __restrict__ emb,
                        float* __restrict__ out)
{
    int t = blockIdx.x;
    int s = t & (SEQ-1);
    int id = tok[t];
    const float* e = emb + (long)id*DM;
    float* o = out + (long)t*DM;
    const float c = -logf(10000.0f) / (float)DM;
    for (int d = threadIdx.x; d < DM; d += blockDim.x) {
        int i2 = d & ~1;
        float ang = (float)s * expf((float)i2 * c);
        float pe = (d & 1) ? cosf(ang) : sinf(ang);
        o[d] = e[d]*32.0f + pe;
    }
}

// ---------------- LayerNorm: warp-per-token ----------------
__global__ void ln_k(const float* __restrict__ x, const float* __restrict__ g,
                     const float* __restrict__ b, bf* __restrict__ out)
{
    int lane = threadIdx.x & 31, w = threadIdx.x >> 5;
    long t = (long)blockIdx.x*8 + w;
    const float4* xr = (const float4*)(x + t*DM);
    float4 v[8];
    float s = 0.f, ss = 0.f;
#pragma unroll
    for (int i=0;i<8;i++){
        v[i] = xr[lane + i*32];
        s  += v[i].x+v[i].y+v[i].z+v[i].w;
        ss += v[i].x*v[i].x+v[i].y*v[i].y+v[i].z*v[i].z+v[i].w*v[i].w;
    }
    s  = warpSum(s);
    ss = warpSum(ss);
    float mean = s * (1.0f/DM);
    float var  = ss * (1.0f/DM) - mean*mean;
    float inv  = rsqrtf(var + 1e-5f);
    uint2* o = (uint2*)(out + t*DM);
#pragma unroll
    for (int i=0;i<8;i++){
        float4 gg = ((const float4*)g)[lane + i*32];
        float4 bb = ((const float4*)b)[lane + i*32];
        uint2 wv;
        wv.x = pack_bf2((v[i].x-mean)*inv*gg.x + bb.x, (v[i].y-mean)*inv*gg.y + bb.y);
        wv.y = pack_bf2((v[i].z-mean)*inv*gg.z + bb.z, (v[i].w-mean)*inv*gg.w + bb.w);
        o[lane + i*32] = wv;
    }
}

// ---------------- log_softmax over NV ----------------
__global__ void logsoftmax_k(float* __restrict__ p)
{
    __shared__ float shm[32], shs[32];
    float* r = p + (long)blockIdx.x * NV;
    int tid = threadIdx.x, lane = tid & 31, w = tid >> 5;

    float m = -3.0e38f, s = 0.f;
    for (int d = tid; d < NV; d += blockDim.x){
        float x = r[d];
        float mn = fmaxf(m, x);
        s = s*__expf(m - mn) + __expf(x - mn);
        m = mn;
    }
#pragma unroll
    for (int o=16;o>0;o>>=1){
        float m2 = __shfl_xor_sync(0xffffffffu, m, o);
        float s2 = __shfl_xor_sync(0xffffffffu, s, o);
        float mn = fmaxf(m, m2);
        s = s*__expf(m-mn) + s2*__expf(m2-mn);
        m = mn;
    }
    if (lane==0){ shm[w] = m; shs[w] = s; }
    __syncthreads();
    if (w==0){
        float mm = (lane < (int)(blockDim.x>>5)) ? shm[lane] : -3.0e38f;
        float ss2 = (lane < (int)(blockDim.x>>5)) ? shs[lane] : 0.f;
#pragma unroll
        for (int o=16;o>0;o>>=1){
            float m2 = __shfl_xor_sync(0xffffffffu, mm, o);
            float s2 = __shfl_xor_sync(0xffffffffu, ss2, o);
            float mn = fmaxf(mm, m2);
            ss2 = ss2*__expf(mm-mn) + s2*__expf(m2-mn);
            mm = mn;
        }
        if (lane==0){ shm[0] = mm; shs[0] = ss2; }
    }
    __syncthreads();
    float lse = shm[0] + logf(shs[0]);
    for (int d = tid; d < NV; d += blockDim.x) r[d] -= lse;
}

// ---------------- host helpers ----------------
static void gemm(const bf* A, const bf* B, const float* bias, const float* res,
                 void* C, int M, int N, int K, int lda, int ldb, int ldc,
                 int gelu, int outBf,
                 long aob=0, long aoh=0, long bob=0, long boh=0, long biasoh=0,
                 long cob=0, long coh=0, int nh=1, int nz=1)
{
    dim3 grid(N/BN, M/128, nz);
    long ctas = (long)grid.x*grid.y*grid.z;
    if (ctas <= 148){
        gemm_ms512<<<grid, 512, GEMM_SMEM128>>>(A,B,bias,res,C,M,N,K,lda,ldb,ldc,gelu,outBf,
                                                aob,aoh,bob,boh,biasoh,cob,coh,nh);
    } else {
        gemm_ms<<<grid, 256, GEMM_SMEM128>>>(A,B,bias,res,C,M,N,K,lda,ldb,ldc,gelu,outBf,
                                             aob,aoh,bob,boh,biasoh,cob,coh,nh);
    }
}

static void cvt(const float* s, bf* d, long n){
    long blocks = (n/8 + 255)/256;
    cvt_k<<<(unsigned)blocks, 256>>>(s, d, n);
}

static void attention(const bf* Hq, const bf* Hkv,
                      const bf* wqkv, const float* bqkv,
                      const bf* wproj, const float* bproj,
                      float* x, int sameKV,
                      bf* QKV, bf* AO)
{
    bf* Q  = QKV;
    bf* Kb = QKV + (size_t)NTOK*DM;
    if (sameKV) {
        gemm(Hq, wqkv, bqkv, nullptr, QKV, NTOK, DM, DM, DM, DM, DM, 0, 1,
             0, 0, 0, (long)DM*DM, DM, 0, (long)NTOK*DM, 3, 3);
    } else {
        gemm(Hq, wqkv, bqkv, nullptr, Q, NTOK, DM, DM, DM, DM, DM, 0, 1);
        gemm(Hkv, wqkv + (size_t)DM*DM, bqkv + DM, nullptr, Kb,
             NTOK, DM, DM, DM, DM, DM, 0, 1,
             0, 0, 0, (long)DM*DM, DM, 0, (long)NTOK*DM, 2, 2);
    }
    bf* Vb = QKV + (size_t)2*NTOK*DM;
    dim3 fgrid(SEQ/FA_BQ, NB*NHD);
    flash_k<<<fgrid, 256, FA_SMEM>>>(Q, Kb, Vb, AO);
    gemm(AO, wproj, bproj, x, x, NTOK, DM, DM, DM, DM, DM, 0, 0);
}

extern "C" void kernel_launch(void* const* d_in, const int* in_sizes, int n_in,
                              void* d_out, int out_size)
{
    const int*   src        = (const int*)  d_in[0];
    const int*   tgt        = (const int*)  d_in[1];
    const float* emb        = (const float*)d_in[5];
    const float* enc_qkv_w  = (const float*)d_in[6];
    const float* enc_qkv_b  = (const float*)d_in[7];
    const float* enc_proj_w = (const float*)d_in[8];
    const float* enc_proj_b = (const float*)d_in[9];
    const float* enc_ff_w1  = (const float*)d_in[10];
    const float* enc_ff_b1  = (const float*)d_in[11];
    const float* enc_ff_w2  = (const float*)d_in[12];
    const float* enc_ff_b2  = (const float*)d_in[13];
    const float* enc_ln_g   = (const float*)d_in[14];
    const float* enc_ln_b   = (const float*)d_in[15];
    const float* enc_norm_g = (const float*)d_in[16];
    const float* enc_norm_b = (const float*)d_in[17];
    const float* dec_qkv_w  = (const float*)d_in[18];
    const float* dec_qkv_b  = (const float*)d_in[19];
    const float* dec_proj_w = (const float*)d_in[20];
    const float* dec_proj_b = (const float*)d_in[21];
    const float* dec_ff_w1  = (const float*)d_in[22];
    const float* dec_ff_b1  = (const float*)d_in[23];
    const float* dec_ff_w2  = (const float*)d_in[24];
    const float* dec_ff_b2  = (const float*)d_in[25];
    const float* dec_ln_g   = (const float*)d_in[26];
    const float* dec_ln_b   = (const float*)d_in[27];
    const float* dec_norm_g = (const float*)d_in[28];
    const float* dec_norm_b = (const float*)d_in[29];
    const float* gen_w      = (const float*)d_in[30];
    const float* gen_b      = (const float*)d_in[31];
    float* out = (float*)d_out;

    cudaFuncSetAttribute(flash_k, cudaFuncAttributeMaxDynamicSharedMemorySize, FA_SMEM);
    cudaFuncSetAttribute(gemm_ms, cudaFuncAttributeMaxDynamicSharedMemorySize, GEMM_SMEM128);
    cudaFuncSetAttribute(gemm_ms512, cudaFuncAttributeMaxDynamicSharedMemorySize, GEMM_SMEM128);

    float *X,*Y;
    bf *Hb,*MEMb,*QKVb,*AOb,*FFb,*W;
    cudaGetSymbolAddress((void**)&X,    g_X);
    cudaGetSymbolAddress((void**)&Y,    g_Y);
    cudaGetSymbolAddress((void**)&Hb,   g_Hb);
    cudaGetSymbolAddress((void**)&MEMb, g_MEMb);
    cudaGetSymbolAddress((void**)&QKVb, g_QKVb);
    cudaGetSymbolAddress((void**)&AOb,  g_AOb);
    cudaGetSymbolAddress((void**)&FFb,  g_FFb);
    cudaGetSymbolAddress((void**)&W,    g_W);

    // ---- one-time (per replay) weight conversion ----
    cvt(enc_qkv_w,  W + O_ENC_QKV,  (long)NLE*3*DM*DM);
    cvt(enc_proj_w, W + O_ENC_PROJ, (long)NLE*DM*DM);
    cvt(enc_ff_w1,  W + O_ENC_FF1,  (long)NLE*DM*HFF);
    cvt(enc_ff_w2,  W + O_ENC_FF2,  (long)NLE*HFF*DM);
    cvt(dec_qkv_w,  W + O_DEC_QKV,  (long)NLD*2*3*DM*DM);
    cvt(dec_proj_w, W + O_DEC_PROJ, (long)NLD*2*DM*DM);
    cvt(dec_ff_w1,  W + O_DEC_FF1,  (long)NLD*DM*HFF);
    cvt(dec_ff_w2,  W + O_DEC_FF2,  (long)NLD*HFF*DM);
    cvt(gen_w,      W + O_GEN,      (long)DM*NV);

    // ---------------- encoder ----------------
    embed_k<<<NTOK,256>>>(src, emb, X);
    for (int l = 0; l < NLE; l++) {
        ln_k<<<NTOK/8,256>>>(X, enc_ln_g + (size_t)(l*2+0)*DM, enc_ln_b + (size_t)(l*2+0)*DM, Hb);
        attention(Hb, Hb,
                  W + O_ENC_QKV + (long)l*3*DM*DM, enc_qkv_b + (size_t)l*3*DM,
                  W + O_ENC_PROJ + (long)l*DM*DM,  enc_proj_b + (size_t)l*DM,
                  X, 1, QKVb, AOb);
        ln_k<<<NTOK/8,256>>>(X, enc_ln_g + (size_t)(l*2+1)*DM, enc_ln_b + (size_t)(l*2+1)*DM, Hb);
        gemm(Hb, W + O_ENC_FF1 + (long)l*DM*HFF, enc_ff_b1 + (size_t)l*HFF, nullptr, FFb,
             NTOK, HFF, DM, DM, HFF, HFF, 1, 1);
        gemm(FFb, W + O_ENC_FF2 + (long)l*HFF*DM, enc_ff_b2 + (size_t)l*DM, X, X,
             NTOK, DM, HFF, HFF, DM, DM, 1, 0);
    }
    ln_k<<<NTOK/8,256>>>(X, enc_norm_g, enc_norm_b, MEMb);

    // ---------------- decoder ----------------
    embed_k<<<NTOK,256>>>(tgt, emb, Y);
    for (int l = 0; l < NLD; l++) {
        ln_k<<<NTOK/8,256>>>(Y, dec_ln_g + (size_t)(l*3+0)*DM, dec_ln_b + (size_t)(l*3+0)*DM, Hb);
        attention(Hb, Hb,
                  W + O_DEC_QKV + (long)(l*2+0)*3*DM*DM, dec_qkv_b + (size_t)(l*2+0)*3*DM,
                  W + O_DEC_PROJ + (long)(l*2+0)*DM*DM,  dec_proj_b + (size_t)(l*2+0)*DM,
                  Y, 1, QKVb, AOb);
        ln_k<<<NTOK/8,256>>>(Y, dec_ln_g + (size_t)(l*3+1)*DM, dec_ln_b + (size_t)(l*3+1)*DM, Hb);
        attention(Hb, MEMb,
                  W + O_DEC_QKV + (long)(l*2+1)*3*DM*DM, dec_qkv_b + (size_t)(l*2+1)*3*DM,
                  W + O_DEC_PROJ + (long)(l*2+1)*DM*DM,  dec_proj_b + (size_t)(l*2+1)*DM,
                  Y, 0, QKVb, AOb);
        ln_k<<<NTOK/8,256>>>(Y, dec_ln_g + (size_t)(l*3+2)*DM, dec_ln_b + (size_t)(l*3+2)*DM, Hb);
        gemm(Hb, W + O_DEC_FF1 + (long)l*DM*HFF, dec_ff_b1 + (size_t)l*HFF, nullptr, FFb,
             NTOK, HFF, DM, DM, HFF, HFF, 1, 1);
        gemm(FFb, W + O_DEC_FF2 + (long)l*HFF*DM, dec_ff_b2 + (size_t)l*DM, Y, Y,
             NTOK, DM, HFF, HFF, DM, DM, 1, 0);
    }
    ln_k<<<NTOK/8,256>>>(Y, dec_norm_g, dec_norm_b, Hb);

    // ---------------- generator + log_softmax ----------------
    gemm(Hb, W + O_GEN, gen_b, nullptr, out, NTOK, NV, DM, DM, NV, NV, 0, 0);
    logsoftmax_k<<<NTOK,256>>>(out);
}